// round 15
// baseline (speedup 1.0000x reference)
#include <cuda_runtime.h>
#include <cstdint>
#include <math.h>

#define TT 256
#define BB 64
#define EE 256
#define HH 512
#define KK 32
#define G4H 2048
#define MROWS (TT*BB)

// ---------------- scratch (static device allocations) ---------------------------
__device__ float    g_xpf[MROWS*G4H];
__device__ float    g_xpr[MROWS*G4H];
__device__ float    g_feats[MROWS*KK];
__device__ float    g_hst[2*2*BB*HH];        // [buf][dir][B][H] fp32 h state
__device__ unsigned g_flags[128];            // per-(dir,sub) step flags
__device__ __align__(16) float g_as[2][MROWS*EE];
__device__ __align__(16) float g_hs[2][MROWS*2*HH];   // splits: L0 out, then L1 out
__device__ __align__(16) float g_w0f[2][G4H*EE];
__device__ __align__(16) float g_w0r[2][G4H*EE];
__device__ __align__(16) float g_w1f[2][G4H*2*HH];
__device__ __align__(16) float g_w1r[2][G4H*2*HH];
__device__ __align__(16) float g_wo[2][KK*2*HH];      // W_out splits

extern __shared__ __align__(16) char dynsmem[];

// ---------------- helpers --------------------------------------------------------
__device__ __forceinline__ float sigm(float x) { return 1.0f / (1.0f + expf(-x)); }

__device__ __forceinline__ void split_tf32(float x, float& hi, float& lo) {
    uint32_t h;
    asm("cvt.rna.tf32.f32 %0, %1;" : "=r"(h) : "f"(x));
    hi = __uint_as_float(h);
    float r = x - hi;
    uint32_t l;
    asm("cvt.rna.tf32.f32 %0, %1;" : "=r"(l) : "f"(r));
    lo = __uint_as_float(l);
}
// cheap split for MMA operands: lo left un-rounded (HW truncates to tf32)
__device__ __forceinline__ void split_tf32_fast(float x, uint32_t& hi, uint32_t& lo) {
    uint32_t h;
    asm("cvt.rna.tf32.f32 %0, %1;" : "=r"(h) : "f"(x));
    hi = h;
    lo = __float_as_uint(x - __uint_as_float(h));
}
__device__ __forceinline__ uint32_t smem_u32(const void* p) {
    uint32_t a;
    asm("{ .reg .u64 t; cvta.to.shared.u64 t, %1; cvt.u32.u64 %0, t; }"
        : "=r"(a) : "l"(p));
    return a;
}
__device__ __forceinline__ void cp16(uint32_t dst, const void* src) {
    asm volatile("cp.async.cg.shared.global [%0], [%1], 16;"
                 :: "r"(dst), "l"(src) : "memory");
}
__device__ __forceinline__ void cp_commit() {
    asm volatile("cp.async.commit_group;" ::: "memory");
}
__device__ __forceinline__ void cp_wait1() {
    asm volatile("cp.async.wait_group 1;" ::: "memory");
}
__device__ __forceinline__ void cp_wait0() {
    asm volatile("cp.async.wait_group 0;" ::: "memory");
}
__device__ __forceinline__ void mma_tf32(float* d, const uint32_t* a,
                                         uint32_t b0, uint32_t b1) {
    asm volatile(
        "mma.sync.aligned.m16n8k8.row.col.f32.tf32.tf32.f32 "
        "{%0,%1,%2,%3}, {%4,%5,%6,%7}, {%8,%9}, {%0,%1,%2,%3};"
        : "+f"(d[0]), "+f"(d[1]), "+f"(d[2]), "+f"(d[3])
        : "r"(a[0]), "r"(a[1]), "r"(a[2]), "r"(a[3]), "r"(b0), "r"(b1));
}

// ---------------- tf32 split kernels ---------------------------------------------
__global__ void split2_kernel(const float* __restrict__ in, float* __restrict__ oh,
                              float* __restrict__ ol, int n4) {
    int i = blockIdx.x * blockDim.x + threadIdx.x;
    if (i >= n4) return;
    float4 a = reinterpret_cast<const float4*>(in)[i];
    float4 h, l;
    split_tf32(a.x, h.x, l.x);
    split_tf32(a.y, h.y, l.y);
    split_tf32(a.z, h.z, l.z);
    split_tf32(a.w, h.w, l.w);
    reinterpret_cast<float4*>(oh)[i] = h;
    reinterpret_cast<float4*>(ol)[i] = l;
}

__global__ void split2_dual_kernel(const float* __restrict__ in0, float* __restrict__ oh0,
                                   float* __restrict__ ol0,
                                   const float* __restrict__ in1, float* __restrict__ oh1,
                                   float* __restrict__ ol1, int n4) {
    int i = blockIdx.x * blockDim.x + threadIdx.x;
    if (i >= 2 * n4) return;
    const float* in; float *oh, *ol; int j;
    if (i < n4) { in = in0; oh = oh0; ol = ol0; j = i; }
    else        { in = in1; oh = oh1; ol = ol1; j = i - n4; }
    float4 a = reinterpret_cast<const float4*>(in)[j];
    float4 h, l;
    split_tf32(a.x, h.x, l.x);
    split_tf32(a.y, h.y, l.y);
    split_tf32(a.z, h.z, l.z);
    split_tf32(a.w, h.w, l.w);
    reinterpret_cast<float4*>(oh)[j] = h;
    reinterpret_cast<float4*>(ol)[j] = l;
}

__global__ void embed_split_kernel(const int* __restrict__ sent,
                                   const float* __restrict__ emb,
                                   float* __restrict__ oh, float* __restrict__ ol) {
    int i = blockIdx.x * blockDim.x + threadIdx.x;
    int total = TT * BB * (EE / 4);
    if (i >= total) return;
    int tb = i >> 6, e4 = i & 63;
    int v = sent[tb];
    float4 a = reinterpret_cast<const float4*>(emb + (size_t)v * EE)[e4];
    float4 h, l;
    split_tf32(a.x, h.x, l.x);
    split_tf32(a.y, h.y, l.y);
    split_tf32(a.z, h.z, l.z);
    split_tf32(a.w, h.w, l.w);
    reinterpret_cast<float4*>(oh)[i] = h;
    reinterpret_cast<float4*>(ol)[i] = l;
}

// ---------------- 3xTF32 mma.sync GEMM (validated round 4) ----------------------
#define TPAD 20
#define TILE_F (128 * TPAD)
#define STAGE_F (4 * TILE_F)
#define GEMM_SMEM (2 * STAGE_F * 4)

__global__ __launch_bounds__(256) void tf32_gemm(
    const float* __restrict__ Ah, const float* __restrict__ Al,
    const float* __restrict__ Wh, const float* __restrict__ Wl,
    const float* __restrict__ bi1, const float* __restrict__ bi2,
    float* __restrict__ C, int K)
{
    float* smem = reinterpret_cast<float*>(dynsmem);
    const uint32_t sb = smem_u32(smem);
    const int tid = threadIdx.x, lane = tid & 31, wid = tid >> 5;
    const int wm = wid & 1, wn = wid >> 1;
    const int bn = blockIdx.x * 128, bm = blockIdx.y * 128;
    const int nch = K >> 4;
    const int qr = lane >> 2, qc = lane & 3;

    float acc[4][4][4];
    #pragma unroll
    for (int mi = 0; mi < 4; mi++)
        #pragma unroll
        for (int ni = 0; ni < 4; ni++)
            #pragma unroll
            for (int q = 0; q < 4; q++) acc[mi][ni][q] = 0.0f;

    auto issue = [&](int c, int st) {
        #pragma unroll
        for (int i = 0; i < 8; i++) {
            int s = tid + i * 256;
            int tile = s >> 9;
            int r = (s >> 2) & 127;
            int sub = s & 3;
            const float* g;
            if (tile == 0)      g = Ah + (size_t)(bm + r) * K + c * 16 + sub * 4;
            else if (tile == 1) g = Al + (size_t)(bm + r) * K + c * 16 + sub * 4;
            else if (tile == 2) g = Wh + (size_t)(bn + r) * K + c * 16 + sub * 4;
            else                g = Wl + (size_t)(bn + r) * K + c * 16 + sub * 4;
            uint32_t d = sb + (uint32_t)(st * STAGE_F + tile * TILE_F + r * TPAD + sub * 4) * 4;
            cp16(d, g);
        }
        cp_commit();
    };

    issue(0, 0);

    for (int c = 0; c < nch; c++) {
        const int st = c & 1;
        if (c + 1 < nch) { issue(c + 1, st ^ 1); cp_wait1(); }
        else cp_wait0();
        __syncthreads();

        const float* Ah_s = smem + st * STAGE_F;
        const float* Al_s = Ah_s + TILE_F;
        const float* Wh_s = Ah_s + 2 * TILE_F;
        const float* Wl_s = Ah_s + 3 * TILE_F;

        #pragma unroll
        for (int s8 = 0; s8 < 16; s8 += 8) {
            #pragma unroll
            for (int t = 0; t < 3; t++) {
                const float* At = (t == 2) ? Al_s : Ah_s;
                const float* Wt = (t == 1) ? Wl_s : Wh_s;
                uint32_t a[4][4];
                #pragma unroll
                for (int mi = 0; mi < 4; mi++) {
                    int m = wm * 64 + mi * 16 + qr;
                    const uint32_t* p =
                        reinterpret_cast<const uint32_t*>(At + m * TPAD + s8 + qc);
                    a[mi][0] = p[0];
                    a[mi][2] = p[4];
                    const uint32_t* p8 =
                        reinterpret_cast<const uint32_t*>(At + (m + 8) * TPAD + s8 + qc);
                    a[mi][1] = p8[0];
                    a[mi][3] = p8[4];
                }
                #pragma unroll
                for (int ni = 0; ni < 4; ni++) {
                    int n = wn * 32 + ni * 8 + qr;
                    const uint32_t* p =
                        reinterpret_cast<const uint32_t*>(Wt + n * TPAD + s8 + qc);
                    uint32_t b0 = p[0], b1 = p[4];
                    #pragma unroll
                    for (int mi = 0; mi < 4; mi++)
                        mma_tf32(acc[mi][ni], a[mi], b0, b1);
                }
            }
        }
        __syncthreads();
    }

    #pragma unroll
    for (int ni = 0; ni < 4; ni++) {
        int col = bn + wn * 32 + ni * 8 + 2 * qc;
        float2 s1 = *reinterpret_cast<const float2*>(bi1 + col);
        float2 s2 = *reinterpret_cast<const float2*>(bi2 + col);
        float bx = s1.x + s2.x, by = s1.y + s2.y;
        #pragma unroll
        for (int mi = 0; mi < 4; mi++) {
            int row = bm + wm * 64 + mi * 16 + qr;
            float2 v0 = make_float2(acc[mi][ni][0] + bx, acc[mi][ni][1] + by);
            float2 v1 = make_float2(acc[mi][ni][2] + bx, acc[mi][ni][3] + by);
            *reinterpret_cast<float2*>(&C[(size_t)row * G4H + col]) = v0;
            *reinterpret_cast<float2*>(&C[(size_t)(row + 8) * G4H + col]) = v1;
        }
    }
}

// ---------------- feats: 3xTF32 MMA (validated round 12) ------------------------
#define FT_PAD 36
#define FT_AF (128 * FT_PAD)
#define FT_BF (32 * FT_PAD)
#define FT_STAGE (2 * (FT_AF + FT_BF))
#define FEATS_SMEM (2 * FT_STAGE * 4)

__global__ __launch_bounds__(256) void feats_gemm(
    const float* __restrict__ Ah, const float* __restrict__ Al,
    const float* __restrict__ Wh, const float* __restrict__ Wl,
    const float* __restrict__ bo, float* __restrict__ C)
{
    float* smem = reinterpret_cast<float*>(dynsmem);
    const uint32_t sb = smem_u32(smem);
    const int tid = threadIdx.x, lane = tid & 31, wid = tid >> 5;
    const int bm = blockIdx.x * 128;
    const int qr = lane >> 2, qc = lane & 3;
    const int K = 2 * HH;
    const int nch = K >> 5;

    float acc[4][4];
    #pragma unroll
    for (int ni = 0; ni < 4; ni++)
        #pragma unroll
        for (int q = 0; q < 4; q++) acc[ni][q] = 0.0f;

    auto issue = [&](int c, int st) {
        #pragma unroll
        for (int i = 0; i < 10; i++) {
            int s = tid + i * 256;
            if (s >= 2560) break;
            const float* g;
            uint32_t off;
            if (s < 1024) {
                int r = s >> 3, seg = s & 7;
                g = Ah + (size_t)(bm + r) * K + c * 32 + seg * 4;
                off = (uint32_t)(r * FT_PAD + seg * 4);
            } else if (s < 2048) {
                int s2 = s - 1024;
                int r = s2 >> 3, seg = s2 & 7;
                g = Al + (size_t)(bm + r) * K + c * 32 + seg * 4;
                off = (uint32_t)(FT_AF + r * FT_PAD + seg * 4);
            } else if (s < 2304) {
                int s2 = s - 2048;
                int r = s2 >> 3, seg = s2 & 7;
                g = Wh + (size_t)r * K + c * 32 + seg * 4;
                off = (uint32_t)(2 * FT_AF + r * FT_PAD + seg * 4);
            } else {
                int s2 = s - 2304;
                int r = s2 >> 3, seg = s2 & 7;
                g = Wl + (size_t)r * K + c * 32 + seg * 4;
                off = (uint32_t)(2 * FT_AF + FT_BF + r * FT_PAD + seg * 4);
            }
            cp16(sb + (uint32_t)(st * FT_STAGE + off) * 4, g);
        }
        cp_commit();
    };

    issue(0, 0);
    for (int c = 0; c < nch; c++) {
        const int st = c & 1;
        if (c + 1 < nch) { issue(c + 1, st ^ 1); cp_wait1(); }
        else cp_wait0();
        __syncthreads();

        const float* Ah_s = smem + st * FT_STAGE;
        const float* Al_s = Ah_s + FT_AF;
        const float* Wh_s = Ah_s + 2 * FT_AF;
        const float* Wl_s = Wh_s + FT_BF;

        #pragma unroll
        for (int s8 = 0; s8 < 32; s8 += 8) {
            const int m = wid * 16 + qr;
            uint32_t ah[4], al[4];
            {
                const uint32_t* p  = reinterpret_cast<const uint32_t*>(Ah_s + m * FT_PAD + s8 + qc);
                const uint32_t* p8 = reinterpret_cast<const uint32_t*>(Ah_s + (m + 8) * FT_PAD + s8 + qc);
                ah[0] = p[0]; ah[1] = p8[0]; ah[2] = p[4]; ah[3] = p8[4];
                const uint32_t* q  = reinterpret_cast<const uint32_t*>(Al_s + m * FT_PAD + s8 + qc);
                const uint32_t* q8 = reinterpret_cast<const uint32_t*>(Al_s + (m + 8) * FT_PAD + s8 + qc);
                al[0] = q[0]; al[1] = q8[0]; al[2] = q[4]; al[3] = q8[4];
            }
            #pragma unroll
            for (int ni = 0; ni < 4; ni++) {
                int n = ni * 8 + qr;
                const uint32_t* p = reinterpret_cast<const uint32_t*>(Wh_s + n * FT_PAD + s8 + qc);
                const uint32_t* q = reinterpret_cast<const uint32_t*>(Wl_s + n * FT_PAD + s8 + qc);
                uint32_t bh0 = p[0], bh1 = p[4];
                uint32_t bl0 = q[0], bl1 = q[4];
                mma_tf32(acc[ni], ah, bh0, bh1);
                mma_tf32(acc[ni], ah, bl0, bl1);
                mma_tf32(acc[ni], al, bh0, bh1);
            }
        }
        __syncthreads();
    }

    #pragma unroll
    for (int ni = 0; ni < 4; ni++) {
        int col = ni * 8 + 2 * qc;
        float2 bb = *reinterpret_cast<const float2*>(bo + col);
        int row = bm + wid * 16 + qr;
        *reinterpret_cast<float2*>(&C[(size_t)row * KK + col]) =
            make_float2(acc[ni][0] + bb.x, acc[ni][1] + bb.y);
        *reinterpret_cast<float2*>(&C[(size_t)(row + 8) * KK + col]) =
            make_float2(acc[ni][2] + bb.x, acc[ni][3] + bb.y);
    }
}

// ---------------- persistent LSTM v7: per-warp flags, throttled polling ----------
// Producer block (dir,sub) posts flags[dir*64+sub]=s+1 at end of step s (after
// fence + syncthreads -> write gating is block-level, so double buffering is
// safe: a block writes buf only after ALL 64 flags >= s+1). Consumer warp w
// polls only its 8 producers via ONE poller (lane 0, 32B sector scan) with
// nanosleep backoff -- fixes the v5 polling storm while keeping per-warp
// skew absorption. Rest identical to validated v6 lean step.
#define HR 516
#define PSD 68
#define OFF_PS (64 * HR * 4)
#define PS_W   (32 * PSD)
#define LSTM7_SMEM (OFF_PS + 8 * PS_W * 4)   // 201728 B

__global__ __launch_bounds__(256, 1) void lstm_mma7_kernel(
    const float* __restrict__ xpf, const float* __restrict__ xpr,
    const float* __restrict__ whf, const float* __restrict__ whr,
    float* hst, float* __restrict__ hb_hi, float* __restrict__ hb_lo,
    unsigned* flags)
{
    float* Hs = reinterpret_cast<float*>(dynsmem);
    float* Ps = reinterpret_cast<float*>(dynsmem + OFF_PS);
    const uint32_t sb = smem_u32(dynsmem);
    const int tid = threadIdx.x, lane = tid & 31, wid = tid >> 5;
    const int dir = blockIdx.x >> 6, sub = blockIdx.x & 63, j0 = sub * 8;
    const float* W  = dir ? whr : whf;
    const float* xp = dir ? xpr : xpf;
    const int qr = lane >> 2, qc = lane & 3;
    const int k0 = wid * 64;

    // gather W_hh fragments (hi & lo) into registers — once per layer
    uint32_t Whi[2][8][4], Wlo[2][8][4];
    #pragma unroll
    for (int At = 0; At < 2; At++) {
        int mA = At * 16 + qr;
        int row0 = (mA >> 3) * 512 + j0 + (mA & 7);
        int mB = mA + 8;
        int row1 = (mB >> 3) * 512 + j0 + (mB & 7);
        #pragma unroll
        for (int ko = 0; ko < 8; ko++) {
            int kb = k0 + ko * 8 + qc;
            float v[4];
            v[0] = W[(size_t)row0 * HH + kb];
            v[1] = W[(size_t)row1 * HH + kb];
            v[2] = W[(size_t)row0 * HH + kb + 4];
            v[3] = W[(size_t)row1 * HH + kb + 4];
            #pragma unroll
            for (int r = 0; r < 4; r++) {
                float h_, l_;
                split_tf32(v[r], h_, l_);
                Whi[At][ko][r] = __float_as_uint(h_);
                Wlo[At][ko][r] = __float_as_uint(l_);
            }
        }
    }

    const int cb0 = tid >> 3,          cj0 = tid & 7;
    const int cb1 = (tid + 256) >> 3;  // same cj
    float cc0 = 0.0f, cc1 = 0.0f;

    for (int s = 0; s < TT; s++) {
        const int rb = s & 1, wb = rb ^ 1;
        const int tt = dir ? (TT - 1 - s) : s;
        const float* xpt = xp + (size_t)tt * BB * G4H;
        const float* hsrc = hst + (size_t)(rb * 2 + dir) * (BB * HH);
        float* hdst = hst + (size_t)(wb * 2 + dir) * (BB * HH);

        // xg loads issued before the wait (execute in its shadow)
        float xg0[4], xg1[4];
        #pragma unroll
        for (int g = 0; g < 4; g++) {
            xg0[g] = xpt[cb0 * G4H + g * HH + j0 + cj0];
            xg1[g] = xpt[cb1 * G4H + g * HH + j0 + cj0];
        }

        // per-warp wait on its 8 producers; single poller + backoff
        if (s > 0) {
            if (lane == 0) {
                const unsigned* f = flags + dir * 64 + 8 * wid;
                for (;;) {
                    int ok = 1;
                    #pragma unroll
                    for (int i = 0; i < 8; i++) {
                        unsigned v;
                        asm volatile("ld.acquire.gpu.global.u32 %0, [%1];"
                                     : "=r"(v) : "l"(f + i) : "memory");
                        ok &= (v >= (unsigned)s);
                    }
                    if (ok) break;
                    __nanosleep(64);
                }
            }
            __syncwarp();
        }

        // per-warp cp.async of this warp's k-slice: 64 rows x 64 floats = 16KB
        #pragma unroll
        for (int i = 0; i < 32; i++) {
            int idx = lane + i * 32;
            int row = idx >> 4, seg = idx & 15;
            cp16(sb + (uint32_t)(row * HR + k0 + seg * 4) * 4,
                 hsrc + (size_t)row * HH + k0 + seg * 4);
        }
        cp_commit();
        cp_wait0();
        __syncwarp();

        float acc[2][8][4];
        #pragma unroll
        for (int At = 0; At < 2; At++)
            #pragma unroll
            for (int nt = 0; nt < 8; nt++)
                #pragma unroll
                for (int q = 0; q < 4; q++) acc[At][nt][q] = 0.0f;

        #pragma unroll
        for (int ko = 0; ko < 8; ko++) {
            #pragma unroll
            for (int nt = 0; nt < 8; nt++) {
                const float* p = Hs + (nt * 8 + qr) * HR + k0 + ko * 8 + qc;
                float b0v = p[0], b1v = p[4];
                uint32_t bh0, bl0, bh1, bl1;
                split_tf32_fast(b0v, bh0, bl0);
                split_tf32_fast(b1v, bh1, bl1);
                #pragma unroll
                for (int At = 0; At < 2; At++) {
                    mma_tf32(acc[At][nt], Whi[At][ko], bh0, bh1);
                    mma_tf32(acc[At][nt], Wlo[At][ko], bh0, bh1);
                    mma_tf32(acc[At][nt], Whi[At][ko], bl0, bl1);
                }
            }
        }

        // stage partials: Ps[wid][m (stride PSD)][n]
        float* Pw = Ps + wid * PS_W;
        #pragma unroll
        for (int At = 0; At < 2; At++)
            #pragma unroll
            for (int nt = 0; nt < 8; nt++) {
                int m = At * 16 + qr, n = nt * 8 + 2 * qc;
                *reinterpret_cast<float2*>(&Pw[m * PSD + n]) =
                    make_float2(acc[At][nt][0], acc[At][nt][1]);
                *reinterpret_cast<float2*>(&Pw[(m + 8) * PSD + n]) =
                    make_float2(acc[At][nt][2], acc[At][nt][3]);
            }
        __syncthreads();

        // cell update: sum the 8 k-partials directly (conflict-free columns)
        float gs0[4], gs1[4];
        #pragma unroll
        for (int g = 0; g < 4; g++) { gs0[g] = 0.f; gs1[g] = 0.f; }
        #pragma unroll
        for (int w = 0; w < 8; w++) {
            const float* P = Ps + w * PS_W;
            #pragma unroll
            for (int g = 0; g < 4; g++) {
                gs0[g] += P[(g * 8 + cj0) * PSD + cb0];
                gs1[g] += P[(g * 8 + cj0) * PSD + cb1];
            }
        }
        cc0 = sigm(gs0[1] + xg0[1]) * cc0 +
              sigm(gs0[0] + xg0[0]) * tanhf(gs0[2] + xg0[2]);
        float hv0 = sigm(gs0[3] + xg0[3]) * tanhf(cc0);
        cc1 = sigm(gs1[1] + xg1[1]) * cc1 +
              sigm(gs1[0] + xg1[0]) * tanhf(gs1[2] + xg1[2]);
        float hv1 = sigm(gs1[3] + xg1[3]) * tanhf(cc1);

        hdst[(size_t)cb0 * HH + j0 + cj0] = hv0;
        hdst[(size_t)cb1 * HH + j0 + cj0] = hv1;

        // make h visible and post this block's flag; split stores after
        if (s + 1 < TT) {
            __threadfence();
            __syncthreads();
            if (tid == 0)
                asm volatile("st.release.gpu.global.u32 [%0], %1;"
                             :: "l"(flags + dir * 64 + sub), "r"((unsigned)(s + 1))
                             : "memory");
        }

        float hh0, hl0, hh1, hl1;
        split_tf32(hv0, hh0, hl0);
        split_tf32(hv1, hh1, hl1);
        size_t o0 = (size_t)(tt * BB + cb0) * (2 * HH) + (size_t)dir * HH + j0 + cj0;
        size_t o1 = (size_t)(tt * BB + cb1) * (2 * HH) + (size_t)dir * HH + j0 + cj0;
        hb_hi[o0] = hh0; hb_lo[o0] = hl0;
        hb_hi[o1] = hh1; hb_lo[o1] = hl1;
    }
}

// ---------------- Viterbi --------------------------------------------------------
__global__ __launch_bounds__(32) void viterbi_kernel(
    const float* __restrict__ feats, const float* __restrict__ trans,
    const float* __restrict__ startt, const float* __restrict__ stopt,
    float* __restrict__ out, int out_size)
{
    int b = blockIdx.x;
    int j = threadIdx.x;
    __shared__ unsigned char bp[TT - 1][KK];
    __shared__ int path[TT];

    float tr[KK];
    #pragma unroll
    for (int k = 0; k < KK; k++) tr[k] = trans[j * KK + k];

    float dp = startt[j] + feats[(size_t)b * KK + j];
    for (int t = 1; t < TT; t++) {
        float best = -INFINITY;
        int arg = 0;
        #pragma unroll
        for (int k = 0; k < KK; k++) {
            float v = tr[k] + __shfl_sync(0xffffffffu, dp, k);
            if (v > best) { best = v; arg = k; }
        }
        bp[t - 1][j] = (unsigned char)arg;
        dp = best + feats[((size_t)t * BB + b) * KK + j];
    }
    dp += stopt[j];

    float bv = dp; int bi = j;
    #pragma unroll
    for (int off = 16; off; off >>= 1) {
        float ov = __shfl_down_sync(0xffffffffu, bv, off);
        int   oi = __shfl_down_sync(0xffffffffu, bi, off);
        if (ov > bv || (ov == bv && oi < bi)) { bv = ov; bi = oi; }
    }
    bv = __shfl_sync(0xffffffffu, bv, 0);
    bi = __shfl_sync(0xffffffffu, bi, 0);

    if (j == 0) {
        path[TT - 1] = bi;
        int tag = bi;
        for (int t = TT - 2; t >= 0; t--) {
            tag = bp[t][tag];
            path[t] = tag;
        }
    }
    __syncwarp();

    int pathsOff = out_size - TT * BB;
    if (pathsOff >= (int)BB) {
        if (j == 0) out[b] = bv;
    } else if (pathsOff < 0) {
        if (j == 0 && b < out_size) out[b] = bv;
        return;
    }
    for (int t = j; t < TT; t += 32)
        out[pathsOff + t * BB + b] = (float)path[t];
}

// ---------------- launch ---------------------------------------------------------
extern "C" void kernel_launch(void* const* d_in, const int* in_sizes, int n_in,
                              void* d_out, int out_size) {
    const int*   sent    = (const int*)d_in[0];
    const float* emb     = (const float*)d_in[1];
    const float* wih_l0f = (const float*)d_in[2];
    const float* whh_l0f = (const float*)d_in[3];
    const float* bih_l0f = (const float*)d_in[4];
    const float* bhh_l0f = (const float*)d_in[5];
    const float* wih_l0r = (const float*)d_in[6];
    const float* whh_l0r = (const float*)d_in[7];
    const float* bih_l0r = (const float*)d_in[8];
    const float* bhh_l0r = (const float*)d_in[9];
    const float* wih_l1f = (const float*)d_in[10];
    const float* whh_l1f = (const float*)d_in[11];
    const float* bih_l1f = (const float*)d_in[12];
    const float* bhh_l1f = (const float*)d_in[13];
    const float* wih_l1r = (const float*)d_in[14];
    const float* whh_l1r = (const float*)d_in[15];
    const float* bih_l1r = (const float*)d_in[16];
    const float* bhh_l1r = (const float*)d_in[17];
    const float* W_out   = (const float*)d_in[18];
    const float* b_out   = (const float*)d_in[19];
    const float* transit = (const float*)d_in[20];
    const float* start_t = (const float*)d_in[21];
    const float* stop_t  = (const float*)d_in[22];

    float *xpf, *xpr, *feats, *hst;
    unsigned* flags;
    cudaGetSymbolAddress((void**)&xpf,   g_xpf);
    cudaGetSymbolAddress((void**)&xpr,   g_xpr);
    cudaGetSymbolAddress((void**)&feats, g_feats);
    cudaGetSymbolAddress((void**)&hst,   g_hst);
    cudaGetSymbolAddress((void**)&flags, g_flags);
    float *as, *hsx, *w0f, *w0r, *w1f, *w1r, *wo;
    cudaGetSymbolAddress((void**)&as,  g_as);
    cudaGetSymbolAddress((void**)&hsx, g_hs);
    cudaGetSymbolAddress((void**)&w0f, g_w0f);
    cudaGetSymbolAddress((void**)&w0r, g_w0r);
    cudaGetSymbolAddress((void**)&w1f, g_w1f);
    cudaGetSymbolAddress((void**)&w1r, g_w1r);
    cudaGetSymbolAddress((void**)&wo,  g_wo);
    const size_t ASZ = (size_t)MROWS*EE, HSZ = (size_t)MROWS*2*HH;
    const size_t W0SZ = (size_t)G4H*EE,  W1SZ = (size_t)G4H*2*HH;
    const size_t WOSZ = (size_t)KK*2*HH;

    cudaFuncSetAttribute(tf32_gemm,
                         cudaFuncAttributeMaxDynamicSharedMemorySize, GEMM_SMEM);
    cudaFuncSetAttribute(feats_gemm,
                         cudaFuncAttributeMaxDynamicSharedMemorySize, FEATS_SMEM);
    cudaFuncSetAttribute(lstm_mma7_kernel,
                         cudaFuncAttributeMaxDynamicSharedMemorySize, LSTM7_SMEM);

    dim3 gg(G4H / 128, MROWS / 128);

    // 1) embedding (fused gather + tf32 split)
    embed_split_kernel<<<(TT * BB * (EE / 4) + 255) / 256, 256>>>(
        sent, emb, as, as + ASZ);

    // 2) split layer-0 weights (both directions, one launch)
    split2_dual_kernel<<<(int)(2*(W0SZ/4) + 255)/256, 256>>>(
        wih_l0f, w0f, w0f + W0SZ, wih_l0r, w0r, w0r + W0SZ, (int)(W0SZ/4));

    // 3-4) layer-0 input projections
    tf32_gemm<<<gg, 256, GEMM_SMEM>>>(as, as + ASZ, w0f, w0f + W0SZ,
                                      bih_l0f, bhh_l0f, xpf, EE);
    tf32_gemm<<<gg, 256, GEMM_SMEM>>>(as, as + ASZ, w0r, w0r + W0SZ,
                                      bih_l0r, bhh_l0r, xpr, EE);

    // 5) layer-0 recurrence; writes h splits into hsx
    cudaMemsetAsync(hst, 0, sizeof(float) * 2 * 2 * BB * HH);
    cudaMemsetAsync(flags, 0, sizeof(unsigned) * 128);
    lstm_mma7_kernel<<<128, 256, LSTM7_SMEM>>>(xpf, xpr, whh_l0f, whh_l0r,
                                               hst, hsx, hsx + HSZ, flags);

    // 6) split layer-1 weights + W_out
    split2_dual_kernel<<<(int)(2*(W1SZ/4) + 255)/256, 256>>>(
        wih_l1f, w1f, w1f + W1SZ, wih_l1r, w1r, w1r + W1SZ, (int)(W1SZ/4));
    split2_kernel<<<(int)(WOSZ/4 + 255)/256, 256>>>(W_out, wo, wo + WOSZ, (int)(WOSZ/4));

    // 7-8) layer-1 input projections (K = 2H)
    tf32_gemm<<<gg, 256, GEMM_SMEM>>>(hsx, hsx + HSZ, w1f, w1f + W1SZ,
                                      bih_l1f, bhh_l1f, xpf, 2 * HH);
    tf32_gemm<<<gg, 256, GEMM_SMEM>>>(hsx, hsx + HSZ, w1r, w1r + W1SZ,
                                      bih_l1r, bhh_l1r, xpr, 2 * HH);

    // 9) layer-1 recurrence; overwrites hsx with layer-1 output splits
    cudaMemsetAsync(hst, 0, sizeof(float) * 2 * 2 * BB * HH);
    cudaMemsetAsync(flags, 0, sizeof(unsigned) * 128);
    lstm_mma7_kernel<<<128, 256, LSTM7_SMEM>>>(xpf, xpr, whh_l1f, whh_l1r,
                                               hst, hsx, hsx + HSZ, flags);

    // 10) emissions via 3xTF32 MMA
    feats_gemm<<<MROWS / 128, 256, FEATS_SMEM>>>(hsx, hsx + HSZ, wo, wo + WOSZ,
                                                 b_out, feats);

    // 11) Viterbi decode + output write
    viterbi_kernel<<<BB, 32>>>(feats, transit, start_t, stop_t, (float*)d_out, out_size);
}

// round 16
// speedup vs baseline: 1.6223x; 1.6223x over previous
#include <cuda_runtime.h>
#include <cstdint>
#include <math.h>

#define TT 256
#define BB 64
#define EE 256
#define HH 512
#define KK 32
#define G4H 2048
#define MROWS (TT*BB)

// ---------------- scratch (static device allocations) ---------------------------
__device__ float    g_xpf[MROWS*G4H];
__device__ float    g_xpr[MROWS*G4H];
__device__ float    g_feats[MROWS*KK];
__device__ float    g_hst[2*2*BB*HH];        // [buf][dir][B][H] fp32 h state
__device__ unsigned g_bar[64];               // dir counters on separate lines
__device__ __align__(16) float g_as[2][MROWS*EE];
__device__ __align__(16) float g_hs[2][MROWS*2*HH];   // splits: L0 out, then L1 out
__device__ __align__(16) float g_w0f[2][G4H*EE];
__device__ __align__(16) float g_w0r[2][G4H*EE];
__device__ __align__(16) float g_w1f[2][G4H*2*HH];
__device__ __align__(16) float g_w1r[2][G4H*2*HH];
__device__ __align__(16) float g_wo[2][KK*2*HH];      // W_out splits

extern __shared__ __align__(16) char dynsmem[];

// ---------------- helpers --------------------------------------------------------
__device__ __forceinline__ float sigm(float x) { return 1.0f / (1.0f + expf(-x)); }

__device__ __forceinline__ void split_tf32(float x, float& hi, float& lo) {
    uint32_t h;
    asm("cvt.rna.tf32.f32 %0, %1;" : "=r"(h) : "f"(x));
    hi = __uint_as_float(h);
    float r = x - hi;
    uint32_t l;
    asm("cvt.rna.tf32.f32 %0, %1;" : "=r"(l) : "f"(r));
    lo = __uint_as_float(l);
}
// cheap split for MMA operands: lo left un-rounded (HW truncates to tf32)
__device__ __forceinline__ void split_tf32_fast(float x, uint32_t& hi, uint32_t& lo) {
    uint32_t h;
    asm("cvt.rna.tf32.f32 %0, %1;" : "=r"(h) : "f"(x));
    hi = h;
    lo = __float_as_uint(x - __uint_as_float(h));
}
__device__ __forceinline__ uint32_t smem_u32(const void* p) {
    uint32_t a;
    asm("{ .reg .u64 t; cvta.to.shared.u64 t, %1; cvt.u32.u64 %0, t; }"
        : "=r"(a) : "l"(p));
    return a;
}
__device__ __forceinline__ void cp16(uint32_t dst, const void* src) {
    asm volatile("cp.async.cg.shared.global [%0], [%1], 16;"
                 :: "r"(dst), "l"(src) : "memory");
}
__device__ __forceinline__ void cp_commit() {
    asm volatile("cp.async.commit_group;" ::: "memory");
}
__device__ __forceinline__ void cp_wait1() {
    asm volatile("cp.async.wait_group 1;" ::: "memory");
}
__device__ __forceinline__ void cp_wait0() {
    asm volatile("cp.async.wait_group 0;" ::: "memory");
}
__device__ __forceinline__ void mma_tf32(float* d, const uint32_t* a,
                                         uint32_t b0, uint32_t b1) {
    asm volatile(
        "mma.sync.aligned.m16n8k8.row.col.f32.tf32.tf32.f32 "
        "{%0,%1,%2,%3}, {%4,%5,%6,%7}, {%8,%9}, {%0,%1,%2,%3};"
        : "+f"(d[0]), "+f"(d[1]), "+f"(d[2]), "+f"(d[3])
        : "r"(a[0]), "r"(a[1]), "r"(a[2]), "r"(a[3]), "r"(b0), "r"(b1));
}

// ---------------- tf32 split kernels ---------------------------------------------
__global__ void split2_kernel(const float* __restrict__ in, float* __restrict__ oh,
                              float* __restrict__ ol, int n4) {
    int i = blockIdx.x * blockDim.x + threadIdx.x;
    if (i >= n4) return;
    float4 a = reinterpret_cast<const float4*>(in)[i];
    float4 h, l;
    split_tf32(a.x, h.x, l.x);
    split_tf32(a.y, h.y, l.y);
    split_tf32(a.z, h.z, l.z);
    split_tf32(a.w, h.w, l.w);
    reinterpret_cast<float4*>(oh)[i] = h;
    reinterpret_cast<float4*>(ol)[i] = l;
}

__global__ void split2_dual_kernel(const float* __restrict__ in0, float* __restrict__ oh0,
                                   float* __restrict__ ol0,
                                   const float* __restrict__ in1, float* __restrict__ oh1,
                                   float* __restrict__ ol1, int n4) {
    int i = blockIdx.x * blockDim.x + threadIdx.x;
    if (i >= 2 * n4) return;
    const float* in; float *oh, *ol; int j;
    if (i < n4) { in = in0; oh = oh0; ol = ol0; j = i; }
    else        { in = in1; oh = oh1; ol = ol1; j = i - n4; }
    float4 a = reinterpret_cast<const float4*>(in)[j];
    float4 h, l;
    split_tf32(a.x, h.x, l.x);
    split_tf32(a.y, h.y, l.y);
    split_tf32(a.z, h.z, l.z);
    split_tf32(a.w, h.w, l.w);
    reinterpret_cast<float4*>(oh)[j] = h;
    reinterpret_cast<float4*>(ol)[j] = l;
}

__global__ void embed_split_kernel(const int* __restrict__ sent,
                                   const float* __restrict__ emb,
                                   float* __restrict__ oh, float* __restrict__ ol) {
    int i = blockIdx.x * blockDim.x + threadIdx.x;
    int total = TT * BB * (EE / 4);
    if (i >= total) return;
    int tb = i >> 6, e4 = i & 63;
    int v = sent[tb];
    float4 a = reinterpret_cast<const float4*>(emb + (size_t)v * EE)[e4];
    float4 h, l;
    split_tf32(a.x, h.x, l.x);
    split_tf32(a.y, h.y, l.y);
    split_tf32(a.z, h.z, l.z);
    split_tf32(a.w, h.w, l.w);
    reinterpret_cast<float4*>(oh)[i] = h;
    reinterpret_cast<float4*>(ol)[i] = l;
}

// ---------------- 3xTF32 mma.sync GEMM (validated round 4) ----------------------
#define TPAD 20
#define TILE_F (128 * TPAD)
#define STAGE_F (4 * TILE_F)
#define GEMM_SMEM (2 * STAGE_F * 4)

__global__ __launch_bounds__(256) void tf32_gemm(
    const float* __restrict__ Ah, const float* __restrict__ Al,
    const float* __restrict__ Wh, const float* __restrict__ Wl,
    const float* __restrict__ bi1, const float* __restrict__ bi2,
    float* __restrict__ C, int K)
{
    float* smem = reinterpret_cast<float*>(dynsmem);
    const uint32_t sb = smem_u32(smem);
    const int tid = threadIdx.x, lane = tid & 31, wid = tid >> 5;
    const int wm = wid & 1, wn = wid >> 1;
    const int bn = blockIdx.x * 128, bm = blockIdx.y * 128;
    const int nch = K >> 4;
    const int qr = lane >> 2, qc = lane & 3;

    float acc[4][4][4];
    #pragma unroll
    for (int mi = 0; mi < 4; mi++)
        #pragma unroll
        for (int ni = 0; ni < 4; ni++)
            #pragma unroll
            for (int q = 0; q < 4; q++) acc[mi][ni][q] = 0.0f;

    auto issue = [&](int c, int st) {
        #pragma unroll
        for (int i = 0; i < 8; i++) {
            int s = tid + i * 256;
            int tile = s >> 9;
            int r = (s >> 2) & 127;
            int sub = s & 3;
            const float* g;
            if (tile == 0)      g = Ah + (size_t)(bm + r) * K + c * 16 + sub * 4;
            else if (tile == 1) g = Al + (size_t)(bm + r) * K + c * 16 + sub * 4;
            else if (tile == 2) g = Wh + (size_t)(bn + r) * K + c * 16 + sub * 4;
            else                g = Wl + (size_t)(bn + r) * K + c * 16 + sub * 4;
            uint32_t d = sb + (uint32_t)(st * STAGE_F + tile * TILE_F + r * TPAD + sub * 4) * 4;
            cp16(d, g);
        }
        cp_commit();
    };

    issue(0, 0);

    for (int c = 0; c < nch; c++) {
        const int st = c & 1;
        if (c + 1 < nch) { issue(c + 1, st ^ 1); cp_wait1(); }
        else cp_wait0();
        __syncthreads();

        const float* Ah_s = smem + st * STAGE_F;
        const float* Al_s = Ah_s + TILE_F;
        const float* Wh_s = Ah_s + 2 * TILE_F;
        const float* Wl_s = Ah_s + 3 * TILE_F;

        #pragma unroll
        for (int s8 = 0; s8 < 16; s8 += 8) {
            #pragma unroll
            for (int t = 0; t < 3; t++) {
                const float* At = (t == 2) ? Al_s : Ah_s;
                const float* Wt = (t == 1) ? Wl_s : Wh_s;
                uint32_t a[4][4];
                #pragma unroll
                for (int mi = 0; mi < 4; mi++) {
                    int m = wm * 64 + mi * 16 + qr;
                    const uint32_t* p =
                        reinterpret_cast<const uint32_t*>(At + m * TPAD + s8 + qc);
                    a[mi][0] = p[0];
                    a[mi][2] = p[4];
                    const uint32_t* p8 =
                        reinterpret_cast<const uint32_t*>(At + (m + 8) * TPAD + s8 + qc);
                    a[mi][1] = p8[0];
                    a[mi][3] = p8[4];
                }
                #pragma unroll
                for (int ni = 0; ni < 4; ni++) {
                    int n = wn * 32 + ni * 8 + qr;
                    const uint32_t* p =
                        reinterpret_cast<const uint32_t*>(Wt + n * TPAD + s8 + qc);
                    uint32_t b0 = p[0], b1 = p[4];
                    #pragma unroll
                    for (int mi = 0; mi < 4; mi++)
                        mma_tf32(acc[mi][ni], a[mi], b0, b1);
                }
            }
        }
        __syncthreads();
    }

    #pragma unroll
    for (int ni = 0; ni < 4; ni++) {
        int col = bn + wn * 32 + ni * 8 + 2 * qc;
        float2 s1 = *reinterpret_cast<const float2*>(bi1 + col);
        float2 s2 = *reinterpret_cast<const float2*>(bi2 + col);
        float bx = s1.x + s2.x, by = s1.y + s2.y;
        #pragma unroll
        for (int mi = 0; mi < 4; mi++) {
            int row = bm + wm * 64 + mi * 16 + qr;
            float2 v0 = make_float2(acc[mi][ni][0] + bx, acc[mi][ni][1] + by);
            float2 v1 = make_float2(acc[mi][ni][2] + bx, acc[mi][ni][3] + by);
            *reinterpret_cast<float2*>(&C[(size_t)row * G4H + col]) = v0;
            *reinterpret_cast<float2*>(&C[(size_t)(row + 8) * G4H + col]) = v1;
        }
    }
}

// ---------------- feats: 3xTF32 MMA (validated round 12) ------------------------
#define FT_PAD 36
#define FT_AF (128 * FT_PAD)
#define FT_BF (32 * FT_PAD)
#define FT_STAGE (2 * (FT_AF + FT_BF))
#define FEATS_SMEM (2 * FT_STAGE * 4)

__global__ __launch_bounds__(256) void feats_gemm(
    const float* __restrict__ Ah, const float* __restrict__ Al,
    const float* __restrict__ Wh, const float* __restrict__ Wl,
    const float* __restrict__ bo, float* __restrict__ C)
{
    float* smem = reinterpret_cast<float*>(dynsmem);
    const uint32_t sb = smem_u32(smem);
    const int tid = threadIdx.x, lane = tid & 31, wid = tid >> 5;
    const int bm = blockIdx.x * 128;
    const int qr = lane >> 2, qc = lane & 3;
    const int K = 2 * HH;
    const int nch = K >> 5;

    float acc[4][4];
    #pragma unroll
    for (int ni = 0; ni < 4; ni++)
        #pragma unroll
        for (int q = 0; q < 4; q++) acc[ni][q] = 0.0f;

    auto issue = [&](int c, int st) {
        #pragma unroll
        for (int i = 0; i < 10; i++) {
            int s = tid + i * 256;
            if (s >= 2560) break;
            const float* g;
            uint32_t off;
            if (s < 1024) {
                int r = s >> 3, seg = s & 7;
                g = Ah + (size_t)(bm + r) * K + c * 32 + seg * 4;
                off = (uint32_t)(r * FT_PAD + seg * 4);
            } else if (s < 2048) {
                int s2 = s - 1024;
                int r = s2 >> 3, seg = s2 & 7;
                g = Al + (size_t)(bm + r) * K + c * 32 + seg * 4;
                off = (uint32_t)(FT_AF + r * FT_PAD + seg * 4);
            } else if (s < 2304) {
                int s2 = s - 2048;
                int r = s2 >> 3, seg = s2 & 7;
                g = Wh + (size_t)r * K + c * 32 + seg * 4;
                off = (uint32_t)(2 * FT_AF + r * FT_PAD + seg * 4);
            } else {
                int s2 = s - 2304;
                int r = s2 >> 3, seg = s2 & 7;
                g = Wl + (size_t)r * K + c * 32 + seg * 4;
                off = (uint32_t)(2 * FT_AF + FT_BF + r * FT_PAD + seg * 4);
            }
            cp16(sb + (uint32_t)(st * FT_STAGE + off) * 4, g);
        }
        cp_commit();
    };

    issue(0, 0);
    for (int c = 0; c < nch; c++) {
        const int st = c & 1;
        if (c + 1 < nch) { issue(c + 1, st ^ 1); cp_wait1(); }
        else cp_wait0();
        __syncthreads();

        const float* Ah_s = smem + st * FT_STAGE;
        const float* Al_s = Ah_s + FT_AF;
        const float* Wh_s = Ah_s + 2 * FT_AF;
        const float* Wl_s = Wh_s + FT_BF;

        #pragma unroll
        for (int s8 = 0; s8 < 32; s8 += 8) {
            const int m = wid * 16 + qr;
            uint32_t ah[4], al[4];
            {
                const uint32_t* p  = reinterpret_cast<const uint32_t*>(Ah_s + m * FT_PAD + s8 + qc);
                const uint32_t* p8 = reinterpret_cast<const uint32_t*>(Ah_s + (m + 8) * FT_PAD + s8 + qc);
                ah[0] = p[0]; ah[1] = p8[0]; ah[2] = p[4]; ah[3] = p8[4];
                const uint32_t* q  = reinterpret_cast<const uint32_t*>(Al_s + m * FT_PAD + s8 + qc);
                const uint32_t* q8 = reinterpret_cast<const uint32_t*>(Al_s + (m + 8) * FT_PAD + s8 + qc);
                al[0] = q[0]; al[1] = q8[0]; al[2] = q[4]; al[3] = q8[4];
            }
            #pragma unroll
            for (int ni = 0; ni < 4; ni++) {
                int n = ni * 8 + qr;
                const uint32_t* p = reinterpret_cast<const uint32_t*>(Wh_s + n * FT_PAD + s8 + qc);
                const uint32_t* q = reinterpret_cast<const uint32_t*>(Wl_s + n * FT_PAD + s8 + qc);
                uint32_t bh0 = p[0], bh1 = p[4];
                uint32_t bl0 = q[0], bl1 = q[4];
                mma_tf32(acc[ni], ah, bh0, bh1);
                mma_tf32(acc[ni], ah, bl0, bl1);
                mma_tf32(acc[ni], al, bh0, bh1);
            }
        }
        __syncthreads();
    }

    #pragma unroll
    for (int ni = 0; ni < 4; ni++) {
        int col = ni * 8 + 2 * qc;
        float2 bb = *reinterpret_cast<const float2*>(bo + col);
        int row = bm + wid * 16 + qr;
        *reinterpret_cast<float2*>(&C[(size_t)row * KK + col]) =
            make_float2(acc[ni][0] + bb.x, acc[ni][1] + bb.y);
        *reinterpret_cast<float2*>(&C[(size_t)(row + 8) * KK + col]) =
            make_float2(acc[ni][2] + bb.x, acc[ni][3] + bb.y);
    }
}

// ---------------- persistent LSTM v8: single counter + pipelined h load ----------
// Round-14 (v6) structure, plus: h cp.async split into two commit groups with MMA
// pipelined over batch halves; release-atomic arrival (no per-thread fence);
// direction counters on separate cache lines.
#define HR 516
#define PSD 68
#define OFF_PS (64 * HR * 4)
#define PS_W   (32 * PSD)
#define LSTM8_SMEM (OFF_PS + 8 * PS_W * 4)   // 201728 B

__global__ __launch_bounds__(256, 1) void lstm_mma8_kernel(
    const float* __restrict__ xpf, const float* __restrict__ xpr,
    const float* __restrict__ whf, const float* __restrict__ whr,
    float* hst, float* __restrict__ hb_hi, float* __restrict__ hb_lo,
    unsigned* bar)
{
    float* Hs = reinterpret_cast<float*>(dynsmem);
    float* Ps = reinterpret_cast<float*>(dynsmem + OFF_PS);
    const uint32_t sb = smem_u32(dynsmem);
    const int tid = threadIdx.x, lane = tid & 31, wid = tid >> 5;
    const int dir = blockIdx.x >> 6, sub = blockIdx.x & 63, j0 = sub * 8;
    const float* W  = dir ? whr : whf;
    const float* xp = dir ? xpr : xpf;
    const int qr = lane >> 2, qc = lane & 3;
    const int k0 = wid * 64;
    unsigned* mybar = bar + dir * 32;        // separate cache line per direction

    // gather W_hh fragments (hi & lo) into registers — once per layer
    uint32_t Whi[2][8][4], Wlo[2][8][4];
    #pragma unroll
    for (int At = 0; At < 2; At++) {
        int mA = At * 16 + qr;
        int row0 = (mA >> 3) * 512 + j0 + (mA & 7);
        int mB = mA + 8;
        int row1 = (mB >> 3) * 512 + j0 + (mB & 7);
        #pragma unroll
        for (int ko = 0; ko < 8; ko++) {
            int kb = k0 + ko * 8 + qc;
            float v[4];
            v[0] = W[(size_t)row0 * HH + kb];
            v[1] = W[(size_t)row1 * HH + kb];
            v[2] = W[(size_t)row0 * HH + kb + 4];
            v[3] = W[(size_t)row1 * HH + kb + 4];
            #pragma unroll
            for (int r = 0; r < 4; r++) {
                float h_, l_;
                split_tf32(v[r], h_, l_);
                Whi[At][ko][r] = __float_as_uint(h_);
                Wlo[At][ko][r] = __float_as_uint(l_);
            }
        }
    }

    const int cb0 = tid >> 3,          cj0 = tid & 7;
    const int cb1 = (tid + 256) >> 3;  // same cj
    float cc0 = 0.0f, cc1 = 0.0f;

    for (int s = 0; s < TT; s++) {
        const int rb = s & 1, wb = rb ^ 1;
        const int tt = dir ? (TT - 1 - s) : s;
        const float* xpt = xp + (size_t)tt * BB * G4H;
        const float* hsrc = hst + (size_t)(rb * 2 + dir) * (BB * HH);
        float* hdst = hst + (size_t)(wb * 2 + dir) * (BB * HH);

        // xg loads issued before the wait (execute in its shadow)
        float xg0[4], xg1[4];
        #pragma unroll
        for (int g = 0; g < 4; g++) {
            xg0[g] = xpt[cb0 * G4H + g * HH + j0 + cj0];
            xg1[g] = xpt[cb1 * G4H + g * HH + j0 + cj0];
        }

        // wait for previous step's h (arrivals posted at end of step s-1)
        if (s > 0) {
            if (tid == 0) {
                unsigned target = 64u * (unsigned)s;
                unsigned v;
                do {
                    asm volatile("ld.acquire.gpu.global.u32 %0, [%1];"
                                 : "=r"(v) : "l"(mybar) : "memory");
                } while (v < target);
            }
            __syncthreads();
        }

        // per-warp cp.async of this warp's k-slice in TWO commit groups
        // (batch rows 0-31, then 32-63); MMA pipelined over the halves.
        #pragma unroll
        for (int i = 0; i < 16; i++) {
            int idx = lane + i * 32;
            int row = idx >> 4, seg = idx & 15;
            cp16(sb + (uint32_t)(row * HR + k0 + seg * 4) * 4,
                 hsrc + (size_t)row * HH + k0 + seg * 4);
        }
        cp_commit();
        #pragma unroll
        for (int i = 16; i < 32; i++) {
            int idx = lane + i * 32;
            int row = idx >> 4, seg = idx & 15;
            cp16(sb + (uint32_t)(row * HR + k0 + seg * 4) * 4,
                 hsrc + (size_t)row * HH + k0 + seg * 4);
        }
        cp_commit();

        float acc[2][8][4];
        #pragma unroll
        for (int At = 0; At < 2; At++)
            #pragma unroll
            for (int nt = 0; nt < 8; nt++)
                #pragma unroll
                for (int q = 0; q < 4; q++) acc[At][nt][q] = 0.0f;

        #pragma unroll
        for (int nh = 0; nh < 2; nh++) {
            if (nh == 0) cp_wait1();
            else         cp_wait0();
            __syncwarp();
            #pragma unroll
            for (int ko = 0; ko < 8; ko++) {
                #pragma unroll
                for (int n2 = 0; n2 < 4; n2++) {
                    const int nt = nh * 4 + n2;
                    const float* p = Hs + (nt * 8 + qr) * HR + k0 + ko * 8 + qc;
                    float b0v = p[0], b1v = p[4];
                    uint32_t bh0, bl0, bh1, bl1;
                    split_tf32_fast(b0v, bh0, bl0);
                    split_tf32_fast(b1v, bh1, bl1);
                    #pragma unroll
                    for (int At = 0; At < 2; At++) {
                        mma_tf32(acc[At][nt], Whi[At][ko], bh0, bh1);
                        mma_tf32(acc[At][nt], Wlo[At][ko], bh0, bh1);
                        mma_tf32(acc[At][nt], Whi[At][ko], bl0, bl1);
                    }
                }
            }
        }

        // stage partials: Ps[wid][m (stride PSD)][n]
        float* Pw = Ps + wid * PS_W;
        #pragma unroll
        for (int At = 0; At < 2; At++)
            #pragma unroll
            for (int nt = 0; nt < 8; nt++) {
                int m = At * 16 + qr, n = nt * 8 + 2 * qc;
                *reinterpret_cast<float2*>(&Pw[m * PSD + n]) =
                    make_float2(acc[At][nt][0], acc[At][nt][1]);
                *reinterpret_cast<float2*>(&Pw[(m + 8) * PSD + n]) =
                    make_float2(acc[At][nt][2], acc[At][nt][3]);
            }
        __syncthreads();

        // cell update: sum the 8 k-partials directly (conflict-free columns)
        float gs0[4], gs1[4];
        #pragma unroll
        for (int g = 0; g < 4; g++) { gs0[g] = 0.f; gs1[g] = 0.f; }
        #pragma unroll
        for (int w = 0; w < 8; w++) {
            const float* P = Ps + w * PS_W;
            #pragma unroll
            for (int g = 0; g < 4; g++) {
                gs0[g] += P[(g * 8 + cj0) * PSD + cb0];
                gs1[g] += P[(g * 8 + cj0) * PSD + cb1];
            }
        }
        cc0 = sigm(gs0[1] + xg0[1]) * cc0 +
              sigm(gs0[0] + xg0[0]) * tanhf(gs0[2] + xg0[2]);
        float hv0 = sigm(gs0[3] + xg0[3]) * tanhf(cc0);
        cc1 = sigm(gs1[1] + xg1[1]) * cc1 +
              sigm(gs1[0] + xg1[0]) * tanhf(gs1[2] + xg1[2]);
        float hv1 = sigm(gs1[3] + xg1[3]) * tanhf(cc1);

        hdst[(size_t)cb0 * HH + j0 + cj0] = hv0;
        hdst[(size_t)cb1 * HH + j0 + cj0] = hv1;

        // publish h + post arrival: CTA barrier orders all threads' stores into
        // tid0's release-atomic (cumulative). Split stores after (off the path).
        if (s + 1 < TT) {
            __syncthreads();
            if (tid == 0)
                asm volatile("red.release.gpu.global.add.u32 [%0], %1;"
                             :: "l"(mybar), "r"(1u) : "memory");
        }

        float hh0, hl0, hh1, hl1;
        split_tf32(hv0, hh0, hl0);
        split_tf32(hv1, hh1, hl1);
        size_t o0 = (size_t)(tt * BB + cb0) * (2 * HH) + (size_t)dir * HH + j0 + cj0;
        size_t o1 = (size_t)(tt * BB + cb1) * (2 * HH) + (size_t)dir * HH + j0 + cj0;
        hb_hi[o0] = hh0; hb_lo[o0] = hl0;
        hb_hi[o1] = hh1; hb_lo[o1] = hl1;
    }
}

// ---------------- Viterbi --------------------------------------------------------
__global__ __launch_bounds__(32) void viterbi_kernel(
    const float* __restrict__ feats, const float* __restrict__ trans,
    const float* __restrict__ startt, const float* __restrict__ stopt,
    float* __restrict__ out, int out_size)
{
    int b = blockIdx.x;
    int j = threadIdx.x;
    __shared__ unsigned char bp[TT - 1][KK];
    __shared__ int path[TT];

    float tr[KK];
    #pragma unroll
    for (int k = 0; k < KK; k++) tr[k] = trans[j * KK + k];

    float dp = startt[j] + feats[(size_t)b * KK + j];
    for (int t = 1; t < TT; t++) {
        float best = -INFINITY;
        int arg = 0;
        #pragma unroll
        for (int k = 0; k < KK; k++) {
            float v = tr[k] + __shfl_sync(0xffffffffu, dp, k);
            if (v > best) { best = v; arg = k; }
        }
        bp[t - 1][j] = (unsigned char)arg;
        dp = best + feats[((size_t)t * BB + b) * KK + j];
    }
    dp += stopt[j];

    float bv = dp; int bi = j;
    #pragma unroll
    for (int off = 16; off; off >>= 1) {
        float ov = __shfl_down_sync(0xffffffffu, bv, off);
        int   oi = __shfl_down_sync(0xffffffffu, bi, off);
        if (ov > bv || (ov == bv && oi < bi)) { bv = ov; bi = oi; }
    }
    bv = __shfl_sync(0xffffffffu, bv, 0);
    bi = __shfl_sync(0xffffffffu, bi, 0);

    if (j == 0) {
        path[TT - 1] = bi;
        int tag = bi;
        for (int t = TT - 2; t >= 0; t--) {
            tag = bp[t][tag];
            path[t] = tag;
        }
    }
    __syncwarp();

    int pathsOff = out_size - TT * BB;
    if (pathsOff >= (int)BB) {
        if (j == 0) out[b] = bv;
    } else if (pathsOff < 0) {
        if (j == 0 && b < out_size) out[b] = bv;
        return;
    }
    for (int t = j; t < TT; t += 32)
        out[pathsOff + t * BB + b] = (float)path[t];
}

// ---------------- launch ---------------------------------------------------------
extern "C" void kernel_launch(void* const* d_in, const int* in_sizes, int n_in,
                              void* d_out, int out_size) {
    const int*   sent    = (const int*)d_in[0];
    const float* emb     = (const float*)d_in[1];
    const float* wih_l0f = (const float*)d_in[2];
    const float* whh_l0f = (const float*)d_in[3];
    const float* bih_l0f = (const float*)d_in[4];
    const float* bhh_l0f = (const float*)d_in[5];
    const float* wih_l0r = (const float*)d_in[6];
    const float* whh_l0r = (const float*)d_in[7];
    const float* bih_l0r = (const float*)d_in[8];
    const float* bhh_l0r = (const float*)d_in[9];
    const float* wih_l1f = (const float*)d_in[10];
    const float* whh_l1f = (const float*)d_in[11];
    const float* bih_l1f = (const float*)d_in[12];
    const float* bhh_l1f = (const float*)d_in[13];
    const float* wih_l1r = (const float*)d_in[14];
    const float* whh_l1r = (const float*)d_in[15];
    const float* bih_l1r = (const float*)d_in[16];
    const float* bhh_l1r = (const float*)d_in[17];
    const float* W_out   = (const float*)d_in[18];
    const float* b_out   = (const float*)d_in[19];
    const float* transit = (const float*)d_in[20];
    const float* start_t = (const float*)d_in[21];
    const float* stop_t  = (const float*)d_in[22];

    float *xpf, *xpr, *feats, *hst;
    unsigned* bar;
    cudaGetSymbolAddress((void**)&xpf,   g_xpf);
    cudaGetSymbolAddress((void**)&xpr,   g_xpr);
    cudaGetSymbolAddress((void**)&feats, g_feats);
    cudaGetSymbolAddress((void**)&hst,   g_hst);
    cudaGetSymbolAddress((void**)&bar,   g_bar);
    float *as, *hsx, *w0f, *w0r, *w1f, *w1r, *wo;
    cudaGetSymbolAddress((void**)&as,  g_as);
    cudaGetSymbolAddress((void**)&hsx, g_hs);
    cudaGetSymbolAddress((void**)&w0f, g_w0f);
    cudaGetSymbolAddress((void**)&w0r, g_w0r);
    cudaGetSymbolAddress((void**)&w1f, g_w1f);
    cudaGetSymbolAddress((void**)&w1r, g_w1r);
    cudaGetSymbolAddress((void**)&wo,  g_wo);
    const size_t ASZ = (size_t)MROWS*EE, HSZ = (size_t)MROWS*2*HH;
    const size_t W0SZ = (size_t)G4H*EE,  W1SZ = (size_t)G4H*2*HH;
    const size_t WOSZ = (size_t)KK*2*HH;

    cudaFuncSetAttribute(tf32_gemm,
                         cudaFuncAttributeMaxDynamicSharedMemorySize, GEMM_SMEM);
    cudaFuncSetAttribute(feats_gemm,
                         cudaFuncAttributeMaxDynamicSharedMemorySize, FEATS_SMEM);
    cudaFuncSetAttribute(lstm_mma8_kernel,
                         cudaFuncAttributeMaxDynamicSharedMemorySize, LSTM8_SMEM);

    dim3 gg(G4H / 128, MROWS / 128);

    // 1) embedding (fused gather + tf32 split)
    embed_split_kernel<<<(TT * BB * (EE / 4) + 255) / 256, 256>>>(
        sent, emb, as, as + ASZ);

    // 2) split layer-0 weights (both directions, one launch)
    split2_dual_kernel<<<(int)(2*(W0SZ/4) + 255)/256, 256>>>(
        wih_l0f, w0f, w0f + W0SZ, wih_l0r, w0r, w0r + W0SZ, (int)(W0SZ/4));

    // 3-4) layer-0 input projections
    tf32_gemm<<<gg, 256, GEMM_SMEM>>>(as, as + ASZ, w0f, w0f + W0SZ,
                                      bih_l0f, bhh_l0f, xpf, EE);
    tf32_gemm<<<gg, 256, GEMM_SMEM>>>(as, as + ASZ, w0r, w0r + W0SZ,
                                      bih_l0r, bhh_l0r, xpr, EE);

    // 5) layer-0 recurrence; writes h splits into hsx
    cudaMemsetAsync(hst, 0, sizeof(float) * 2 * 2 * BB * HH);
    cudaMemsetAsync(bar, 0, sizeof(unsigned) * 64);
    lstm_mma8_kernel<<<128, 256, LSTM8_SMEM>>>(xpf, xpr, whh_l0f, whh_l0r,
                                               hst, hsx, hsx + HSZ, bar);

    // 6) split layer-1 weights + W_out
    split2_dual_kernel<<<(int)(2*(W1SZ/4) + 255)/256, 256>>>(
        wih_l1f, w1f, w1f + W1SZ, wih_l1r, w1r, w1r + W1SZ, (int)(W1SZ/4));
    split2_kernel<<<(int)(WOSZ/4 + 255)/256, 256>>>(W_out, wo, wo + WOSZ, (int)(WOSZ/4));

    // 7-8) layer-1 input projections (K = 2H)
    tf32_gemm<<<gg, 256, GEMM_SMEM>>>(hsx, hsx + HSZ, w1f, w1f + W1SZ,
                                      bih_l1f, bhh_l1f, xpf, 2 * HH);
    tf32_gemm<<<gg, 256, GEMM_SMEM>>>(hsx, hsx + HSZ, w1r, w1r + W1SZ,
                                      bih_l1r, bhh_l1r, xpr, 2 * HH);

    // 9) layer-1 recurrence; overwrites hsx with layer-1 output splits
    cudaMemsetAsync(hst, 0, sizeof(float) * 2 * 2 * BB * HH);
    cudaMemsetAsync(bar, 0, sizeof(unsigned) * 64);
    lstm_mma8_kernel<<<128, 256, LSTM8_SMEM>>>(xpf, xpr, whh_l1f, whh_l1r,
                                               hst, hsx, hsx + HSZ, bar);

    // 10) emissions via 3xTF32 MMA
    feats_gemm<<<MROWS / 128, 256, FEATS_SMEM>>>(hsx, hsx + HSZ, wo, wo + WOSZ,
                                                 b_out, feats);

    // 11) Viterbi decode + output write
    viterbi_kernel<<<BB, 32>>>(feats, transit, start_t, stop_t, (float*)d_out, out_size);
}

// round 17
// speedup vs baseline: 1.6421x; 1.0122x over previous
#include <cuda_runtime.h>
#include <cstdint>
#include <math.h>

#define TT 256
#define BB 64
#define EE 256
#define HH 512
#define KK 32
#define G4H 2048
#define MROWS (TT*BB)

// ---------------- scratch (static device allocations) ---------------------------
__device__ float    g_xpf[MROWS*G4H];
__device__ float    g_xpr[MROWS*G4H];
__device__ float    g_feats[MROWS*KK];
__device__ float    g_hst[2*2*BB*HH];        // [buf][dir][B][H] fp32 h state
__device__ unsigned g_bar[64];               // dir counters on separate lines
__device__ __align__(16) float g_as[2][MROWS*EE];
__device__ __align__(16) float g_hs[2][MROWS*2*HH];   // splits: L0 out, then L1 out
__device__ __align__(16) float g_w0f[2][G4H*EE];
__device__ __align__(16) float g_w0r[2][G4H*EE];
__device__ __align__(16) float g_w1f[2][G4H*2*HH];
__device__ __align__(16) float g_w1r[2][G4H*2*HH];
__device__ __align__(16) float g_wo[2][KK*2*HH];      // W_out splits

extern __shared__ __align__(16) char dynsmem[];

// ---------------- helpers --------------------------------------------------------
__device__ __forceinline__ float sigm(float x) { return 1.0f / (1.0f + expf(-x)); }

__device__ __forceinline__ void split_tf32(float x, float& hi, float& lo) {
    uint32_t h;
    asm("cvt.rna.tf32.f32 %0, %1;" : "=r"(h) : "f"(x));
    hi = __uint_as_float(h);
    float r = x - hi;
    uint32_t l;
    asm("cvt.rna.tf32.f32 %0, %1;" : "=r"(l) : "f"(r));
    lo = __uint_as_float(l);
}
// cheap split for MMA operands: lo left un-rounded (HW truncates to tf32)
__device__ __forceinline__ void split_tf32_fast(float x, uint32_t& hi, uint32_t& lo) {
    uint32_t h;
    asm("cvt.rna.tf32.f32 %0, %1;" : "=r"(h) : "f"(x));
    hi = h;
    lo = __float_as_uint(x - __uint_as_float(h));
}
__device__ __forceinline__ uint32_t smem_u32(const void* p) {
    uint32_t a;
    asm("{ .reg .u64 t; cvta.to.shared.u64 t, %1; cvt.u32.u64 %0, t; }"
        : "=r"(a) : "l"(p));
    return a;
}
__device__ __forceinline__ void cp16(uint32_t dst, const void* src) {
    asm volatile("cp.async.cg.shared.global [%0], [%1], 16;"
                 :: "r"(dst), "l"(src) : "memory");
}
__device__ __forceinline__ void cp_commit() {
    asm volatile("cp.async.commit_group;" ::: "memory");
}
__device__ __forceinline__ void cp_wait1() {
    asm volatile("cp.async.wait_group 1;" ::: "memory");
}
__device__ __forceinline__ void cp_wait0() {
    asm volatile("cp.async.wait_group 0;" ::: "memory");
}
__device__ __forceinline__ void mma_tf32(float* d, const uint32_t* a,
                                         uint32_t b0, uint32_t b1) {
    asm volatile(
        "mma.sync.aligned.m16n8k8.row.col.f32.tf32.tf32.f32 "
        "{%0,%1,%2,%3}, {%4,%5,%6,%7}, {%8,%9}, {%0,%1,%2,%3};"
        : "+f"(d[0]), "+f"(d[1]), "+f"(d[2]), "+f"(d[3])
        : "r"(a[0]), "r"(a[1]), "r"(a[2]), "r"(a[3]), "r"(b0), "r"(b1));
}

// ---------------- tf32 split kernels ---------------------------------------------
__global__ void split2_kernel(const float* __restrict__ in, float* __restrict__ oh,
                              float* __restrict__ ol, int n4) {
    int i = blockIdx.x * blockDim.x + threadIdx.x;
    if (i >= n4) return;
    float4 a = reinterpret_cast<const float4*>(in)[i];
    float4 h, l;
    split_tf32(a.x, h.x, l.x);
    split_tf32(a.y, h.y, l.y);
    split_tf32(a.z, h.z, l.z);
    split_tf32(a.w, h.w, l.w);
    reinterpret_cast<float4*>(oh)[i] = h;
    reinterpret_cast<float4*>(ol)[i] = l;
}

__global__ void split2_dual_kernel(const float* __restrict__ in0, float* __restrict__ oh0,
                                   float* __restrict__ ol0,
                                   const float* __restrict__ in1, float* __restrict__ oh1,
                                   float* __restrict__ ol1, int n4) {
    int i = blockIdx.x * blockDim.x + threadIdx.x;
    if (i >= 2 * n4) return;
    const float* in; float *oh, *ol; int j;
    if (i < n4) { in = in0; oh = oh0; ol = ol0; j = i; }
    else        { in = in1; oh = oh1; ol = ol1; j = i - n4; }
    float4 a = reinterpret_cast<const float4*>(in)[j];
    float4 h, l;
    split_tf32(a.x, h.x, l.x);
    split_tf32(a.y, h.y, l.y);
    split_tf32(a.z, h.z, l.z);
    split_tf32(a.w, h.w, l.w);
    reinterpret_cast<float4*>(oh)[j] = h;
    reinterpret_cast<float4*>(ol)[j] = l;
}

__global__ void embed_split_kernel(const int* __restrict__ sent,
                                   const float* __restrict__ emb,
                                   float* __restrict__ oh, float* __restrict__ ol) {
    int i = blockIdx.x * blockDim.x + threadIdx.x;
    int total = TT * BB * (EE / 4);
    if (i >= total) return;
    int tb = i >> 6, e4 = i & 63;
    int v = sent[tb];
    float4 a = reinterpret_cast<const float4*>(emb + (size_t)v * EE)[e4];
    float4 h, l;
    split_tf32(a.x, h.x, l.x);
    split_tf32(a.y, h.y, l.y);
    split_tf32(a.z, h.z, l.z);
    split_tf32(a.w, h.w, l.w);
    reinterpret_cast<float4*>(oh)[i] = h;
    reinterpret_cast<float4*>(ol)[i] = l;
}

// ---------------- 3xTF32 mma.sync GEMM (round 4 + A-frag reuse) -----------------
// Inner loop restructured: Ah fragments loaded ONCE (used by terms hh and hl),
// then registers reused for Al (term lh). 56 LDS per k8-chunk per warp vs 72,
// same peak register pressure. __launch_bounds__(256,2) pins 2 CTAs/SM.
#define TPAD 20
#define TILE_F (128 * TPAD)
#define STAGE_F (4 * TILE_F)
#define GEMM_SMEM (2 * STAGE_F * 4)

__global__ __launch_bounds__(256, 2) void tf32_gemm(
    const float* __restrict__ Ah, const float* __restrict__ Al,
    const float* __restrict__ Wh, const float* __restrict__ Wl,
    const float* __restrict__ bi1, const float* __restrict__ bi2,
    float* __restrict__ C, int K)
{
    float* smem = reinterpret_cast<float*>(dynsmem);
    const uint32_t sb = smem_u32(smem);
    const int tid = threadIdx.x, lane = tid & 31, wid = tid >> 5;
    const int wm = wid & 1, wn = wid >> 1;
    const int bn = blockIdx.x * 128, bm = blockIdx.y * 128;
    const int nch = K >> 4;
    const int qr = lane >> 2, qc = lane & 3;

    float acc[4][4][4];
    #pragma unroll
    for (int mi = 0; mi < 4; mi++)
        #pragma unroll
        for (int ni = 0; ni < 4; ni++)
            #pragma unroll
            for (int q = 0; q < 4; q++) acc[mi][ni][q] = 0.0f;

    auto issue = [&](int c, int st) {
        #pragma unroll
        for (int i = 0; i < 8; i++) {
            int s = tid + i * 256;
            int tile = s >> 9;
            int r = (s >> 2) & 127;
            int sub = s & 3;
            const float* g;
            if (tile == 0)      g = Ah + (size_t)(bm + r) * K + c * 16 + sub * 4;
            else if (tile == 1) g = Al + (size_t)(bm + r) * K + c * 16 + sub * 4;
            else if (tile == 2) g = Wh + (size_t)(bn + r) * K + c * 16 + sub * 4;
            else                g = Wl + (size_t)(bn + r) * K + c * 16 + sub * 4;
            uint32_t d = sb + (uint32_t)(st * STAGE_F + tile * TILE_F + r * TPAD + sub * 4) * 4;
            cp16(d, g);
        }
        cp_commit();
    };

    issue(0, 0);

    for (int c = 0; c < nch; c++) {
        const int st = c & 1;
        if (c + 1 < nch) { issue(c + 1, st ^ 1); cp_wait1(); }
        else cp_wait0();
        __syncthreads();

        const float* Ah_s = smem + st * STAGE_F;
        const float* Al_s = Ah_s + TILE_F;
        const float* Wh_s = Ah_s + 2 * TILE_F;
        const float* Wl_s = Ah_s + 3 * TILE_F;

        #pragma unroll
        for (int s8 = 0; s8 < 16; s8 += 8) {
            uint32_t a[4][4];
            // phase 1: load Ah frags once; terms hh + hl
            #pragma unroll
            for (int mi = 0; mi < 4; mi++) {
                int m = wm * 64 + mi * 16 + qr;
                const uint32_t* p =
                    reinterpret_cast<const uint32_t*>(Ah_s + m * TPAD + s8 + qc);
                const uint32_t* p8 =
                    reinterpret_cast<const uint32_t*>(Ah_s + (m + 8) * TPAD + s8 + qc);
                a[mi][0] = p[0]; a[mi][1] = p8[0];
                a[mi][2] = p[4]; a[mi][3] = p8[4];
            }
            #pragma unroll
            for (int ni = 0; ni < 4; ni++) {
                int n = wn * 32 + ni * 8 + qr;
                const uint32_t* ph =
                    reinterpret_cast<const uint32_t*>(Wh_s + n * TPAD + s8 + qc);
                const uint32_t* pl =
                    reinterpret_cast<const uint32_t*>(Wl_s + n * TPAD + s8 + qc);
                uint32_t bh0 = ph[0], bh1 = ph[4];
                uint32_t bl0 = pl[0], bl1 = pl[4];
                #pragma unroll
                for (int mi = 0; mi < 4; mi++) {
                    mma_tf32(acc[mi][ni], a[mi], bh0, bh1);
                    mma_tf32(acc[mi][ni], a[mi], bl0, bl1);
                }
            }
            // phase 2: reuse regs for Al frags; term lh
            #pragma unroll
            for (int mi = 0; mi < 4; mi++) {
                int m = wm * 64 + mi * 16 + qr;
                const uint32_t* p =
                    reinterpret_cast<const uint32_t*>(Al_s + m * TPAD + s8 + qc);
                const uint32_t* p8 =
                    reinterpret_cast<const uint32_t*>(Al_s + (m + 8) * TPAD + s8 + qc);
                a[mi][0] = p[0]; a[mi][1] = p8[0];
                a[mi][2] = p[4]; a[mi][3] = p8[4];
            }
            #pragma unroll
            for (int ni = 0; ni < 4; ni++) {
                int n = wn * 32 + ni * 8 + qr;
                const uint32_t* ph =
                    reinterpret_cast<const uint32_t*>(Wh_s + n * TPAD + s8 + qc);
                uint32_t bh0 = ph[0], bh1 = ph[4];
                #pragma unroll
                for (int mi = 0; mi < 4; mi++)
                    mma_tf32(acc[mi][ni], a[mi], bh0, bh1);
            }
        }
        __syncthreads();
    }

    #pragma unroll
    for (int ni = 0; ni < 4; ni++) {
        int col = bn + wn * 32 + ni * 8 + 2 * qc;
        float2 s1 = *reinterpret_cast<const float2*>(bi1 + col);
        float2 s2 = *reinterpret_cast<const float2*>(bi2 + col);
        float bx = s1.x + s2.x, by = s1.y + s2.y;
        #pragma unroll
        for (int mi = 0; mi < 4; mi++) {
            int row = bm + wm * 64 + mi * 16 + qr;
            float2 v0 = make_float2(acc[mi][ni][0] + bx, acc[mi][ni][1] + by);
            float2 v1 = make_float2(acc[mi][ni][2] + bx, acc[mi][ni][3] + by);
            *reinterpret_cast<float2*>(&C[(size_t)row * G4H + col]) = v0;
            *reinterpret_cast<float2*>(&C[(size_t)(row + 8) * G4H + col]) = v1;
        }
    }
}

// ---------------- feats: 3xTF32 MMA (validated round 12) ------------------------
#define FT_PAD 36
#define FT_AF (128 * FT_PAD)
#define FT_BF (32 * FT_PAD)
#define FT_STAGE (2 * (FT_AF + FT_BF))
#define FEATS_SMEM (2 * FT_STAGE * 4)

__global__ __launch_bounds__(256) void feats_gemm(
    const float* __restrict__ Ah, const float* __restrict__ Al,
    const float* __restrict__ Wh, const float* __restrict__ Wl,
    const float* __restrict__ bo, float* __restrict__ C)
{
    float* smem = reinterpret_cast<float*>(dynsmem);
    const uint32_t sb = smem_u32(smem);
    const int tid = threadIdx.x, lane = tid & 31, wid = tid >> 5;
    const int bm = blockIdx.x * 128;
    const int qr = lane >> 2, qc = lane & 3;
    const int K = 2 * HH;
    const int nch = K >> 5;

    float acc[4][4];
    #pragma unroll
    for (int ni = 0; ni < 4; ni++)
        #pragma unroll
        for (int q = 0; q < 4; q++) acc[ni][q] = 0.0f;

    auto issue = [&](int c, int st) {
        #pragma unroll
        for (int i = 0; i < 10; i++) {
            int s = tid + i * 256;
            if (s >= 2560) break;
            const float* g;
            uint32_t off;
            if (s < 1024) {
                int r = s >> 3, seg = s & 7;
                g = Ah + (size_t)(bm + r) * K + c * 32 + seg * 4;
                off = (uint32_t)(r * FT_PAD + seg * 4);
            } else if (s < 2048) {
                int s2 = s - 1024;
                int r = s2 >> 3, seg = s2 & 7;
                g = Al + (size_t)(bm + r) * K + c * 32 + seg * 4;
                off = (uint32_t)(FT_AF + r * FT_PAD + seg * 4);
            } else if (s < 2304) {
                int s2 = s - 2048;
                int r = s2 >> 3, seg = s2 & 7;
                g = Wh + (size_t)r * K + c * 32 + seg * 4;
                off = (uint32_t)(2 * FT_AF + r * FT_PAD + seg * 4);
            } else {
                int s2 = s - 2304;
                int r = s2 >> 3, seg = s2 & 7;
                g = Wl + (size_t)r * K + c * 32 + seg * 4;
                off = (uint32_t)(2 * FT_AF + FT_BF + r * FT_PAD + seg * 4);
            }
            cp16(sb + (uint32_t)(st * FT_STAGE + off) * 4, g);
        }
        cp_commit();
    };

    issue(0, 0);
    for (int c = 0; c < nch; c++) {
        const int st = c & 1;
        if (c + 1 < nch) { issue(c + 1, st ^ 1); cp_wait1(); }
        else cp_wait0();
        __syncthreads();

        const float* Ah_s = smem + st * FT_STAGE;
        const float* Al_s = Ah_s + FT_AF;
        const float* Wh_s = Ah_s + 2 * FT_AF;
        const float* Wl_s = Wh_s + FT_BF;

        #pragma unroll
        for (int s8 = 0; s8 < 32; s8 += 8) {
            const int m = wid * 16 + qr;
            uint32_t ah[4], al[4];
            {
                const uint32_t* p  = reinterpret_cast<const uint32_t*>(Ah_s + m * FT_PAD + s8 + qc);
                const uint32_t* p8 = reinterpret_cast<const uint32_t*>(Ah_s + (m + 8) * FT_PAD + s8 + qc);
                ah[0] = p[0]; ah[1] = p8[0]; ah[2] = p[4]; ah[3] = p8[4];
                const uint32_t* q  = reinterpret_cast<const uint32_t*>(Al_s + m * FT_PAD + s8 + qc);
                const uint32_t* q8 = reinterpret_cast<const uint32_t*>(Al_s + (m + 8) * FT_PAD + s8 + qc);
                al[0] = q[0]; al[1] = q8[0]; al[2] = q[4]; al[3] = q8[4];
            }
            #pragma unroll
            for (int ni = 0; ni < 4; ni++) {
                int n = ni * 8 + qr;
                const uint32_t* p = reinterpret_cast<const uint32_t*>(Wh_s + n * FT_PAD + s8 + qc);
                const uint32_t* q = reinterpret_cast<const uint32_t*>(Wl_s + n * FT_PAD + s8 + qc);
                uint32_t bh0 = p[0], bh1 = p[4];
                uint32_t bl0 = q[0], bl1 = q[4];
                mma_tf32(acc[ni], ah, bh0, bh1);
                mma_tf32(acc[ni], ah, bl0, bl1);
                mma_tf32(acc[ni], al, bh0, bh1);
            }
        }
        __syncthreads();
    }

    #pragma unroll
    for (int ni = 0; ni < 4; ni++) {
        int col = ni * 8 + 2 * qc;
        float2 bb = *reinterpret_cast<const float2*>(bo + col);
        int row = bm + wid * 16 + qr;
        *reinterpret_cast<float2*>(&C[(size_t)row * KK + col]) =
            make_float2(acc[ni][0] + bb.x, acc[ni][1] + bb.y);
        *reinterpret_cast<float2*>(&C[(size_t)(row + 8) * KK + col]) =
            make_float2(acc[ni][2] + bb.x, acc[ni][3] + bb.y);
    }
}

// ---------------- persistent LSTM v8 (validated round 16) ------------------------
#define HR 516
#define PSD 68
#define OFF_PS (64 * HR * 4)
#define PS_W   (32 * PSD)
#define LSTM8_SMEM (OFF_PS + 8 * PS_W * 4)   // 201728 B

__global__ __launch_bounds__(256, 1) void lstm_mma8_kernel(
    const float* __restrict__ xpf, const float* __restrict__ xpr,
    const float* __restrict__ whf, const float* __restrict__ whr,
    float* hst, float* __restrict__ hb_hi, float* __restrict__ hb_lo,
    unsigned* bar)
{
    float* Hs = reinterpret_cast<float*>(dynsmem);
    float* Ps = reinterpret_cast<float*>(dynsmem + OFF_PS);
    const uint32_t sb = smem_u32(dynsmem);
    const int tid = threadIdx.x, lane = tid & 31, wid = tid >> 5;
    const int dir = blockIdx.x >> 6, sub = blockIdx.x & 63, j0 = sub * 8;
    const float* W  = dir ? whr : whf;
    const float* xp = dir ? xpr : xpf;
    const int qr = lane >> 2, qc = lane & 3;
    const int k0 = wid * 64;
    unsigned* mybar = bar + dir * 32;

    uint32_t Whi[2][8][4], Wlo[2][8][4];
    #pragma unroll
    for (int At = 0; At < 2; At++) {
        int mA = At * 16 + qr;
        int row0 = (mA >> 3) * 512 + j0 + (mA & 7);
        int mB = mA + 8;
        int row1 = (mB >> 3) * 512 + j0 + (mB & 7);
        #pragma unroll
        for (int ko = 0; ko < 8; ko++) {
            int kb = k0 + ko * 8 + qc;
            float v[4];
            v[0] = W[(size_t)row0 * HH + kb];
            v[1] = W[(size_t)row1 * HH + kb];
            v[2] = W[(size_t)row0 * HH + kb + 4];
            v[3] = W[(size_t)row1 * HH + kb + 4];
            #pragma unroll
            for (int r = 0; r < 4; r++) {
                float h_, l_;
                split_tf32(v[r], h_, l_);
                Whi[At][ko][r] = __float_as_uint(h_);
                Wlo[At][ko][r] = __float_as_uint(l_);
            }
        }
    }

    const int cb0 = tid >> 3,          cj0 = tid & 7;
    const int cb1 = (tid + 256) >> 3;
    float cc0 = 0.0f, cc1 = 0.0f;

    for (int s = 0; s < TT; s++) {
        const int rb = s & 1, wb = rb ^ 1;
        const int tt = dir ? (TT - 1 - s) : s;
        const float* xpt = xp + (size_t)tt * BB * G4H;
        const float* hsrc = hst + (size_t)(rb * 2 + dir) * (BB * HH);
        float* hdst = hst + (size_t)(wb * 2 + dir) * (BB * HH);

        float xg0[4], xg1[4];
        #pragma unroll
        for (int g = 0; g < 4; g++) {
            xg0[g] = xpt[cb0 * G4H + g * HH + j0 + cj0];
            xg1[g] = xpt[cb1 * G4H + g * HH + j0 + cj0];
        }

        if (s > 0) {
            if (tid == 0) {
                unsigned target = 64u * (unsigned)s;
                unsigned v;
                do {
                    asm volatile("ld.acquire.gpu.global.u32 %0, [%1];"
                                 : "=r"(v) : "l"(mybar) : "memory");
                } while (v < target);
            }
            __syncthreads();
        }

        #pragma unroll
        for (int i = 0; i < 16; i++) {
            int idx = lane + i * 32;
            int row = idx >> 4, seg = idx & 15;
            cp16(sb + (uint32_t)(row * HR + k0 + seg * 4) * 4,
                 hsrc + (size_t)row * HH + k0 + seg * 4);
        }
        cp_commit();
        #pragma unroll
        for (int i = 16; i < 32; i++) {
            int idx = lane + i * 32;
            int row = idx >> 4, seg = idx & 15;
            cp16(sb + (uint32_t)(row * HR + k0 + seg * 4) * 4,
                 hsrc + (size_t)row * HH + k0 + seg * 4);
        }
        cp_commit();

        float acc[2][8][4];
        #pragma unroll
        for (int At = 0; At < 2; At++)
            #pragma unroll
            for (int nt = 0; nt < 8; nt++)
                #pragma unroll
                for (int q = 0; q < 4; q++) acc[At][nt][q] = 0.0f;

        #pragma unroll
        for (int nh = 0; nh < 2; nh++) {
            if (nh == 0) cp_wait1();
            else         cp_wait0();
            __syncwarp();
            #pragma unroll
            for (int ko = 0; ko < 8; ko++) {
                #pragma unroll
                for (int n2 = 0; n2 < 4; n2++) {
                    const int nt = nh * 4 + n2;
                    const float* p = Hs + (nt * 8 + qr) * HR + k0 + ko * 8 + qc;
                    float b0v = p[0], b1v = p[4];
                    uint32_t bh0, bl0, bh1, bl1;
                    split_tf32_fast(b0v, bh0, bl0);
                    split_tf32_fast(b1v, bh1, bl1);
                    #pragma unroll
                    for (int At = 0; At < 2; At++) {
                        mma_tf32(acc[At][nt], Whi[At][ko], bh0, bh1);
                        mma_tf32(acc[At][nt], Wlo[At][ko], bh0, bh1);
                        mma_tf32(acc[At][nt], Whi[At][ko], bl0, bl1);
                    }
                }
            }
        }

        float* Pw = Ps + wid * PS_W;
        #pragma unroll
        for (int At = 0; At < 2; At++)
            #pragma unroll
            for (int nt = 0; nt < 8; nt++) {
                int m = At * 16 + qr, n = nt * 8 + 2 * qc;
                *reinterpret_cast<float2*>(&Pw[m * PSD + n]) =
                    make_float2(acc[At][nt][0], acc[At][nt][1]);
                *reinterpret_cast<float2*>(&Pw[(m + 8) * PSD + n]) =
                    make_float2(acc[At][nt][2], acc[At][nt][3]);
            }
        __syncthreads();

        float gs0[4], gs1[4];
        #pragma unroll
        for (int g = 0; g < 4; g++) { gs0[g] = 0.f; gs1[g] = 0.f; }
        #pragma unroll
        for (int w = 0; w < 8; w++) {
            const float* P = Ps + w * PS_W;
            #pragma unroll
            for (int g = 0; g < 4; g++) {
                gs0[g] += P[(g * 8 + cj0) * PSD + cb0];
                gs1[g] += P[(g * 8 + cj0) * PSD + cb1];
            }
        }
        cc0 = sigm(gs0[1] + xg0[1]) * cc0 +
              sigm(gs0[0] + xg0[0]) * tanhf(gs0[2] + xg0[2]);
        float hv0 = sigm(gs0[3] + xg0[3]) * tanhf(cc0);
        cc1 = sigm(gs1[1] + xg1[1]) * cc1 +
              sigm(gs1[0] + xg1[0]) * tanhf(gs1[2] + xg1[2]);
        float hv1 = sigm(gs1[3] + xg1[3]) * tanhf(cc1);

        hdst[(size_t)cb0 * HH + j0 + cj0] = hv0;
        hdst[(size_t)cb1 * HH + j0 + cj0] = hv1;

        if (s + 1 < TT) {
            __syncthreads();
            if (tid == 0)
                asm volatile("red.release.gpu.global.add.u32 [%0], %1;"
                             :: "l"(mybar), "r"(1u) : "memory");
        }

        float hh0, hl0, hh1, hl1;
        split_tf32(hv0, hh0, hl0);
        split_tf32(hv1, hh1, hl1);
        size_t o0 = (size_t)(tt * BB + cb0) * (2 * HH) + (size_t)dir * HH + j0 + cj0;
        size_t o1 = (size_t)(tt * BB + cb1) * (2 * HH) + (size_t)dir * HH + j0 + cj0;
        hb_hi[o0] = hh0; hb_lo[o0] = hl0;
        hb_hi[o1] = hh1; hb_lo[o1] = hl1;
    }
}

// ---------------- Viterbi --------------------------------------------------------
__global__ __launch_bounds__(32) void viterbi_kernel(
    const float* __restrict__ feats, const float* __restrict__ trans,
    const float* __restrict__ startt, const float* __restrict__ stopt,
    float* __restrict__ out, int out_size)
{
    int b = blockIdx.x;
    int j = threadIdx.x;
    __shared__ unsigned char bp[TT - 1][KK];
    __shared__ int path[TT];

    float tr[KK];
    #pragma unroll
    for (int k = 0; k < KK; k++) tr[k] = trans[j * KK + k];

    float dp = startt[j] + feats[(size_t)b * KK + j];
    for (int t = 1; t < TT; t++) {
        float best = -INFINITY;
        int arg = 0;
        #pragma unroll
        for (int k = 0; k < KK; k++) {
            float v = tr[k] + __shfl_sync(0xffffffffu, dp, k);
            if (v > best) { best = v; arg = k; }
        }
        bp[t - 1][j] = (unsigned char)arg;
        dp = best + feats[((size_t)t * BB + b) * KK + j];
    }
    dp += stopt[j];

    float bv = dp; int bi = j;
    #pragma unroll
    for (int off = 16; off; off >>= 1) {
        float ov = __shfl_down_sync(0xffffffffu, bv, off);
        int   oi = __shfl_down_sync(0xffffffffu, bi, off);
        if (ov > bv || (ov == bv && oi < bi)) { bv = ov; bi = oi; }
    }
    bv = __shfl_sync(0xffffffffu, bv, 0);
    bi = __shfl_sync(0xffffffffu, bi, 0);

    if (j == 0) {
        path[TT - 1] = bi;
        int tag = bi;
        for (int t = TT - 2; t >= 0; t--) {
            tag = bp[t][tag];
            path[t] = tag;
        }
    }
    __syncwarp();

    int pathsOff = out_size - TT * BB;
    if (pathsOff >= (int)BB) {
        if (j == 0) out[b] = bv;
    } else if (pathsOff < 0) {
        if (j == 0 && b < out_size) out[b] = bv;
        return;
    }
    for (int t = j; t < TT; t += 32)
        out[pathsOff + t * BB + b] = (float)path[t];
}

// ---------------- launch ---------------------------------------------------------
extern "C" void kernel_launch(void* const* d_in, const int* in_sizes, int n_in,
                              void* d_out, int out_size) {
    const int*   sent    = (const int*)d_in[0];
    const float* emb     = (const float*)d_in[1];
    const float* wih_l0f = (const float*)d_in[2];
    const float* whh_l0f = (const float*)d_in[3];
    const float* bih_l0f = (const float*)d_in[4];
    const float* bhh_l0f = (const float*)d_in[5];
    const float* wih_l0r = (const float*)d_in[6];
    const float* whh_l0r = (const float*)d_in[7];
    const float* bih_l0r = (const float*)d_in[8];
    const float* bhh_l0r = (const float*)d_in[9];
    const float* wih_l1f = (const float*)d_in[10];
    const float* whh_l1f = (const float*)d_in[11];
    const float* bih_l1f = (const float*)d_in[12];
    const float* bhh_l1f = (const float*)d_in[13];
    const float* wih_l1r = (const float*)d_in[14];
    const float* whh_l1r = (const float*)d_in[15];
    const float* bih_l1r = (const float*)d_in[16];
    const float* bhh_l1r = (const float*)d_in[17];
    const float* W_out   = (const float*)d_in[18];
    const float* b_out   = (const float*)d_in[19];
    const float* transit = (const float*)d_in[20];
    const float* start_t = (const float*)d_in[21];
    const float* stop_t  = (const float*)d_in[22];

    float *xpf, *xpr, *feats, *hst;
    unsigned* bar;
    cudaGetSymbolAddress((void**)&xpf,   g_xpf);
    cudaGetSymbolAddress((void**)&xpr,   g_xpr);
    cudaGetSymbolAddress((void**)&feats, g_feats);
    cudaGetSymbolAddress((void**)&hst,   g_hst);
    cudaGetSymbolAddress((void**)&bar,   g_bar);
    float *as, *hsx, *w0f, *w0r, *w1f, *w1r, *wo;
    cudaGetSymbolAddress((void**)&as,  g_as);
    cudaGetSymbolAddress((void**)&hsx, g_hs);
    cudaGetSymbolAddress((void**)&w0f, g_w0f);
    cudaGetSymbolAddress((void**)&w0r, g_w0r);
    cudaGetSymbolAddress((void**)&w1f, g_w1f);
    cudaGetSymbolAddress((void**)&w1r, g_w1r);
    cudaGetSymbolAddress((void**)&wo,  g_wo);
    const size_t ASZ = (size_t)MROWS*EE, HSZ = (size_t)MROWS*2*HH;
    const size_t W0SZ = (size_t)G4H*EE,  W1SZ = (size_t)G4H*2*HH;
    const size_t WOSZ = (size_t)KK*2*HH;

    cudaFuncSetAttribute(tf32_gemm,
                         cudaFuncAttributeMaxDynamicSharedMemorySize, GEMM_SMEM);
    cudaFuncSetAttribute(feats_gemm,
                         cudaFuncAttributeMaxDynamicSharedMemorySize, FEATS_SMEM);
    cudaFuncSetAttribute(lstm_mma8_kernel,
                         cudaFuncAttributeMaxDynamicSharedMemorySize, LSTM8_SMEM);

    dim3 gg(G4H / 128, MROWS / 128);

    // 1) embedding (fused gather + tf32 split)
    embed_split_kernel<<<(TT * BB * (EE / 4) + 255) / 256, 256>>>(
        sent, emb, as, as + ASZ);

    // 2) split layer-0 weights (both directions, one launch)
    split2_dual_kernel<<<(int)(2*(W0SZ/4) + 255)/256, 256>>>(
        wih_l0f, w0f, w0f + W0SZ, wih_l0r, w0r, w0r + W0SZ, (int)(W0SZ/4));

    // 3-4) layer-0 input projections
    tf32_gemm<<<gg, 256, GEMM_SMEM>>>(as, as + ASZ, w0f, w0f + W0SZ,
                                      bih_l0f, bhh_l0f, xpf, EE);
    tf32_gemm<<<gg, 256, GEMM_SMEM>>>(as, as + ASZ, w0r, w0r + W0SZ,
                                      bih_l0r, bhh_l0r, xpr, EE);

    // 5) layer-0 recurrence; writes h splits into hsx
    cudaMemsetAsync(hst, 0, sizeof(float) * 2 * 2 * BB * HH);
    cudaMemsetAsync(bar, 0, sizeof(unsigned) * 64);
    lstm_mma8_kernel<<<128, 256, LSTM8_SMEM>>>(xpf, xpr, whh_l0f, whh_l0r,
                                               hst, hsx, hsx + HSZ, bar);

    // 6) split layer-1 weights + W_out
    split2_dual_kernel<<<(int)(2*(W1SZ/4) + 255)/256, 256>>>(
        wih_l1f, w1f, w1f + W1SZ, wih_l1r, w1r, w1r + W1SZ, (int)(W1SZ/4));
    split2_kernel<<<(int)(WOSZ/4 + 255)/256, 256>>>(W_out, wo, wo + WOSZ, (int)(WOSZ/4));

    // 7-8) layer-1 input projections (K = 2H)
    tf32_gemm<<<gg, 256, GEMM_SMEM>>>(hsx, hsx + HSZ, w1f, w1f + W1SZ,
                                      bih_l1f, bhh_l1f, xpf, 2 * HH);
    tf32_gemm<<<gg, 256, GEMM_SMEM>>>(hsx, hsx + HSZ, w1r, w1r + W1SZ,
                                      bih_l1r, bhh_l1r, xpr, 2 * HH);

    // 9) layer-1 recurrence; overwrites hsx with layer-1 output splits
    cudaMemsetAsync(hst, 0, sizeof(float) * 2 * 2 * BB * HH);
    cudaMemsetAsync(bar, 0, sizeof(unsigned) * 64);
    lstm_mma8_kernel<<<128, 256, LSTM8_SMEM>>>(xpf, xpr, whh_l1f, whh_l1r,
                                               hst, hsx, hsx + HSZ, bar);

    // 10) emissions via 3xTF32 MMA
    feats_gemm<<<MROWS / 128, 256, FEATS_SMEM>>>(hsx, hsx + HSZ, wo, wo + WOSZ,
                                                 b_out, feats);

    // 11) Viterbi decode + output write
    viterbi_kernel<<<BB, 32>>>(feats, transit, start_t, stop_t, (float*)d_out, out_size);
}